// round 12
// baseline (speedup 1.0000x reference)
#include <cuda_runtime.h>
#include <cuda_fp16.h>
#include <stdint.h>
#include <math.h>

// Problem constants (fixed by the dataset)
#define NN 50000
#define EE 850000

// ---------------- scratch (device globals; no allocation allowed) -----------
__device__ __half2 g_feat_h2[NN * 6 * 16]; // fc output as half2, [n][H][16]
__device__ float g_h1[NN * 128];     // layer-1 output
__device__ float g_h2[NN * 128];     // layer-2 output
__device__ float g_res3[NN * 192];   // h2 @ resW3
__device__ float g_rst3[NN * 192];   // layer-3 output (pre-mean)
__device__ float g_el[NN * 6];
__device__ float g_er[NN * 6];
__device__ int   g_offs[NN + 1];
__device__ int   g_deg[NN];
__device__ int   g_cur[NN];
__device__ int   g_csrc[EE];         // src node per incoming edge, bucketed by dst

// ---------------- CSR build -------------------------------------------------
__global__ void k_zero(int n) {
    int i = blockIdx.x * blockDim.x + threadIdx.x;
    if (i < n) { g_deg[i] = 0; g_cur[i] = 0; }
}

__global__ void k_deg(const int* __restrict__ dst, int e) {
    int i = blockIdx.x * blockDim.x + threadIdx.x;
    if (i < e) atomicAdd(&g_deg[dst[i]], 1);
}

// single-block scan: serial-per-thread + warp-shuffle block scan (2 barriers)
__global__ void k_scan(int n) {
    __shared__ int ws[32];
    int t = threadIdx.x;
    int per = (n + 1023) / 1024;
    int start = t * per;
    int end = min(start + per, n);

    int sum = 0;
    for (int i = start; i < end; i++) sum += g_deg[i];

    int lane = t & 31, wid = t >> 5;
    int v = sum;
#pragma unroll
    for (int o = 1; o < 32; o <<= 1) {
        int u = __shfl_up_sync(0xffffffffu, v, o);
        if (lane >= o) v += u;
    }
    if (lane == 31) ws[wid] = v;
    __syncthreads();
    if (wid == 0) {
        int s = ws[lane];
#pragma unroll
        for (int o = 1; o < 32; o <<= 1) {
            int u = __shfl_up_sync(0xffffffffu, s, o);
            if (lane >= o) s += u;
        }
        ws[lane] = s;
    }
    __syncthreads();

    int warp_base = wid ? ws[wid - 1] : 0;
    int run = warp_base + v - sum;          // exclusive prefix for this thread
    for (int i = start; i < end; i++) {
        g_offs[i] = run;
        run += g_deg[i];
    }
    if (t == 0) g_offs[n] = ws[31];
}

__global__ void k_fill(const int* __restrict__ src, const int* __restrict__ dst, int e) {
    int i = blockIdx.x * blockDim.x + threadIdx.x;
    if (i < e) {
        int d = dst[i];
        int p = g_offs[d] + atomicAdd(&g_cur[d], 1);
        g_csrc[p] = src[i];
    }
}

// ---------------- tf32 helpers ----------------------------------------------
__device__ __forceinline__ float to_tf32(float x) {
    uint32_t u;
    asm("cvt.rna.tf32.f32 %0, %1;" : "=r"(u) : "f"(x));
    return __uint_as_float(u);
}

__device__ __forceinline__ void mma8(float* c, uint32_t a0, uint32_t a1,
                                     uint32_t a2, uint32_t a3,
                                     uint32_t b0, uint32_t b1) {
    asm volatile(
        "mma.sync.aligned.m16n8k8.row.col.f32.tf32.tf32.f32 "
        "{%0,%1,%2,%3}, {%4,%5,%6,%7}, {%8,%9}, {%0,%1,%2,%3};"
        : "+f"(c[0]), "+f"(c[1]), "+f"(c[2]), "+f"(c[3])
        : "r"(a0), "r"(a1), "r"(a2), "r"(a3), "r"(b0), "r"(b1));
}

// ---------------- tf32 tensor-core GEMM + fused epilogue --------------------
// C[n][m] = A[n][128] @ W[128][m]; block 64x64, 8 warps, warp tile 16x32.
// Full W column (128x64) resident in SMEM -> ONE barrier, flat 16-step
// mainloop, deep LDS->mma software pipelining.
// Epilogue options: write_c (fp32 C for resW3), do_attn (half2 feat + el/er).
__global__ void k_gemm(const float* __restrict__ A, const float* __restrict__ W,
                       float* __restrict__ C, int n, int m,
                       const float* __restrict__ al, const float* __restrict__ ar,
                       int H, int write_c, int do_attn) {
    __shared__ float As[64][132];  // fragment loads: bank = 4g+tig, conflict-free
    __shared__ float Wf[128][72];  // fragment loads: bank = 8tig+g, conflict-free

    int row0 = blockIdx.x * 64;
    int col0 = blockIdx.y * 64;
    int t = threadIdx.x;
    int lane = t & 31, w = t >> 5;
    int wm = w & 3;                // 4 m-groups of 16 rows
    int wn = w >> 2;               // 2 n-groups of 32 cols (= 1 head)
    int g = lane >> 2, tig = lane & 3;

    // stage full A tile (64x128), converting to tf32
#pragma unroll
    for (int i = t; i < 64 * 32; i += 256) {
        int r = i >> 5, c4 = i & 31;
        int gr = row0 + r;
        float4 v = make_float4(0.f, 0.f, 0.f, 0.f);
        if (gr < n) v = *(const float4*)&A[(size_t)gr * 128 + c4 * 4];
        v.x = to_tf32(v.x); v.y = to_tf32(v.y);
        v.z = to_tf32(v.z); v.w = to_tf32(v.w);
        *(float4*)&As[r][c4 * 4] = v;
    }

    // stage full W column (128 k x 64 cols), converting to tf32
#pragma unroll
    for (int i = t; i < 128 * 16; i += 256) {
        int kk = i >> 4, c4 = i & 15;
        float4 v = *(const float4*)&W[(size_t)kk * m + col0 + c4 * 4];
        v.x = to_tf32(v.x); v.y = to_tf32(v.y);
        v.z = to_tf32(v.z); v.w = to_tf32(v.w);
        *(float4*)&Wf[kk][c4 * 4] = v;
    }
    __syncthreads();               // the only barrier

    float acc[4][4] = {};          // [n-tile][c-frag]
    int ra = wm * 16 + g;

#pragma unroll
    for (int ks = 0; ks < 16; ks++) {
        int kb = ks * 8;
        uint32_t a0 = __float_as_uint(As[ra][kb + tig]);
        uint32_t a1 = __float_as_uint(As[ra + 8][kb + tig]);
        uint32_t a2 = __float_as_uint(As[ra][kb + tig + 4]);
        uint32_t a3 = __float_as_uint(As[ra + 8][kb + tig + 4]);
#pragma unroll
        for (int nt = 0; nt < 4; nt++) {
            int cb = wn * 32 + nt * 8 + g;
            uint32_t b0 = __float_as_uint(Wf[kb + tig][cb]);
            uint32_t b1 = __float_as_uint(Wf[kb + tig + 4][cb]);
            mma8(acc[nt], a0, a1, a2, a3, b0, b1);
        }
    }

    int r_lo = row0 + wm * 16 + g;
    int r_hi = r_lo + 8;

    if (write_c) {
#pragma unroll
        for (int nt = 0; nt < 4; nt++) {
            int c = col0 + wn * 32 + nt * 8 + 2 * tig;
            if (r_lo < n)
                *(float2*)&C[(size_t)r_lo * m + c] = make_float2(acc[nt][0], acc[nt][1]);
            if (r_hi < n)
                *(float2*)&C[(size_t)r_hi * m + c] = make_float2(acc[nt][2], acc[nt][3]);
        }
    }

    if (do_attn) {
        int h = (col0 >> 5) + wn;  // global head index
        float pel_lo = 0.f, per_lo = 0.f, pel_hi = 0.f, per_hi = 0.f;
#pragma unroll
        for (int nt = 0; nt < 4; nt++) {
            int ci = nt * 8 + 2 * tig;     // col within head
            float2 alv = *(const float2*)&al[h * 32 + ci];
            float2 arv = *(const float2*)&ar[h * 32 + ci];
            pel_lo += acc[nt][0] * alv.x + acc[nt][1] * alv.y;
            per_lo += acc[nt][0] * arv.x + acc[nt][1] * arv.y;
            pel_hi += acc[nt][2] * alv.x + acc[nt][3] * alv.y;
            per_hi += acc[nt][2] * arv.x + acc[nt][3] * arv.y;

            __half2 plo = __floats2half2_rn(acc[nt][0], acc[nt][1]);
            __half2 phi = __floats2half2_rn(acc[nt][2], acc[nt][3]);
            int hw = nt * 4 + tig;         // half2 index within head
            if (r_lo < n) g_feat_h2[((size_t)r_lo * H + h) * 16 + hw] = plo;
            if (r_hi < n) g_feat_h2[((size_t)r_hi * H + h) * 16 + hw] = phi;
        }
#pragma unroll
        for (int o = 1; o < 4; o <<= 1) {
            pel_lo += __shfl_xor_sync(0xffffffffu, pel_lo, o);
            per_lo += __shfl_xor_sync(0xffffffffu, per_lo, o);
            pel_hi += __shfl_xor_sync(0xffffffffu, pel_hi, o);
            per_hi += __shfl_xor_sync(0xffffffffu, per_hi, o);
        }
        if (tig == 0) {
            if (r_lo < n) { g_el[r_lo * H + h] = pel_lo; g_er[r_lo * H + h] = per_lo; }
            if (r_hi < n) { g_el[r_hi * H + h] = pel_hi; g_er[r_hi * H + h] = per_hi; }
        }
    }
}

// ---------------- fused aggregation: inline exp(leaky(el+er)) ---------------
// HG heads handled per task; LPT = 8*HG lanes per task.
//   H=4: HG=4 -> warp per node (csrc broadcast once per node).
//   H=6: HG=2 -> half-warp per (node, head-pair).
template<int H, int HG>
__global__ void k_aggf(const float* __restrict__ residual,  // [n][H*32] or null
                       const float* __restrict__ bias,      // [H*32]
                       float* __restrict__ out,             // [n][H*32]
                       int n, int do_relu) {
    constexpr int LPT = 8 * HG;       // lanes per task
    constexpr int TPW = 32 / LPT;     // tasks per warp
    constexpr int NB = H / HG;        // head-blocks per node

    int gwarp = (blockIdx.x * blockDim.x + threadIdx.x) >> 5;
    int lane = threadIdx.x & 31;
    int sub = lane / LPT;
    int sl = lane % LPT;
    int task = gwarp * TPW + sub;
    if (task >= n * NB) return;

    int v = task / NB;
    int hb = (task % NB) * HG;
    int h = hb + (sl >> 3);
    int fp = sl & 7;

    float er_d = g_er[v * H + h];
    int beg = g_offs[v], end = g_offs[v + 1];

    float a0 = 0.f, a1 = 0.f, a2 = 0.f, a3 = 0.f, den = 0.f;
#pragma unroll 4
    for (int i = beg; i < end; i++) {
        int s = g_csrc[i];
        float x = g_el[s * H + h] + er_d;
        x = (x > 0.f) ? x : 0.2f * x;
        float wgt = __expf(x);
        den += wgt;
        uint2 raw = *(const uint2*)&g_feat_h2[((size_t)s * H + h) * 16 + fp * 2];
        float2 f0 = __half22float2(*(const __half2*)&raw.x);
        float2 f1 = __half22float2(*(const __half2*)&raw.y);
        a0 = fmaf(wgt, f0.x, a0);
        a1 = fmaf(wgt, f0.y, a1);
        a2 = fmaf(wgt, f1.x, a2);
        a3 = fmaf(wgt, f1.y, a3);
    }
    float inv = 1.f / fmaxf(den, 1e-9f);
    a0 *= inv; a1 *= inv; a2 *= inv; a3 *= inv;

    size_t o = ((size_t)v * H + h) * 32 + fp * 4;
    if (residual) {
        float4 r4 = *(const float4*)&residual[o];
        a0 += r4.x; a1 += r4.y; a2 += r4.z; a3 += r4.w;
    }
    float4 b4 = *(const float4*)&bias[h * 32 + fp * 4];
    a0 += b4.x; a1 += b4.y; a2 += b4.z; a3 += b4.w;
    if (do_relu) {
        a0 = fmaxf(a0, 0.f); a1 = fmaxf(a1, 0.f);
        a2 = fmaxf(a2, 0.f); a3 = fmaxf(a3, 0.f);
    }
    *(float4*)&out[o] = make_float4(a0, a1, a2, a3);
}

// ---------------- mean over 6 heads -----------------------------------------
__global__ void k_mean(float* __restrict__ out, int n) {
    int i = blockIdx.x * blockDim.x + threadIdx.x;
    if (i < n * 32) {
        int v = i >> 5, k = i & 31;
        float s = 0.f;
#pragma unroll
        for (int h = 0; h < 6; h++) s += g_rst3[(size_t)v * 192 + h * 32 + k];
        out[i] = s * (1.f / 6.f);
    }
}

// ---------------- launch ----------------------------------------------------
extern "C" void kernel_launch(void* const* d_in, const int* in_sizes, int n_in,
                              void* d_out, int out_size) {
    const float* x     = (const float*)d_in[0];
    const int*   src   = (const int*)d_in[1];
    const int*   dst   = (const int*)d_in[2];
    const float* W1    = (const float*)d_in[3];
    const float* al1   = (const float*)d_in[4];
    const float* ar1   = (const float*)d_in[5];
    const float* b1    = (const float*)d_in[6];
    const float* W2    = (const float*)d_in[7];
    const float* al2   = (const float*)d_in[8];
    const float* ar2   = (const float*)d_in[9];
    const float* b2    = (const float*)d_in[10];
    const float* W3    = (const float*)d_in[11];
    const float* al3   = (const float*)d_in[12];
    const float* ar3   = (const float*)d_in[13];
    const float* b3    = (const float*)d_in[14];
    const float* resW3 = (const float*)d_in[15];

    int n = in_sizes[0] / 128;   // 50000
    int e = in_sizes[1];         // 850000

    float *p_h1, *p_h2, *p_res3, *p_rst3;
    cudaGetSymbolAddress((void**)&p_h1,   g_h1);
    cudaGetSymbolAddress((void**)&p_h2,   g_h2);
    cudaGetSymbolAddress((void**)&p_res3, g_res3);
    cudaGetSymbolAddress((void**)&p_rst3, g_rst3);

    // CSR build (graph fixed, but rebuilt deterministically each replay)
    k_zero<<<(n + 255) / 256, 256>>>(n);
    k_deg<<<(e + 255) / 256, 256>>>(dst, e);
    k_scan<<<1, 1024>>>(n);
    k_fill<<<(e + 255) / 256, 256>>>(src, dst, e);

    dim3 gemm_grid_128((n + 63) / 64, 128 / 64);
    dim3 gemm_grid_192((n + 63) / 64, 192 / 64);

    // agg grids: H=4 -> n warps; H=6 -> 3n half-warps
    int agg4_blocks = (n * 32 + 255) / 256;
    int agg6_blocks = (((n * 3 + 1) / 2) * 32 + 255) / 256;

    // ---- layer 1: H=4 ----
    k_gemm<<<gemm_grid_128, 256>>>(x, W1, nullptr, n, 128, al1, ar1, 4, 0, 1);
    k_aggf<4, 4><<<agg4_blocks, 256>>>(nullptr, b1, p_h1, n, 1);

    // ---- layer 2: H=4, identity residual ----
    k_gemm<<<gemm_grid_128, 256>>>(p_h1, W2, nullptr, n, 128, al2, ar2, 4, 0, 1);
    k_aggf<4, 4><<<agg4_blocks, 256>>>(p_h1, b2, p_h2, n, 1);

    // ---- layer 3: H=6, projected residual, no relu ----
    k_gemm<<<gemm_grid_192, 256>>>(p_h2, resW3, p_res3, n, 192, nullptr, nullptr, 6, 1, 0);
    k_gemm<<<gemm_grid_192, 256>>>(p_h2, W3, nullptr, n, 192, al3, ar3, 6, 0, 1);
    k_aggf<6, 2><<<agg6_blocks, 256>>>(p_res3, b3, p_rst3, n, 0);

    // ---- mean over heads ----
    k_mean<<<(n * 32 + 255) / 256, 256>>>((float*)d_out, n);
}

// round 15
// speedup vs baseline: 1.0192x; 1.0192x over previous
#include <cuda_runtime.h>
#include <cuda_fp16.h>
#include <stdint.h>
#include <math.h>

// Problem constants (fixed by the dataset)
#define NN 50000
#define EE 850000

// ---------------- scratch (device globals; no allocation allowed) -----------
__device__ __half2 g_feat_h2[NN * 6 * 16]; // fc output as half2, [n][H][16]
__device__ float g_h1[NN * 128];     // layer-1 output
__device__ float g_h2[NN * 128];     // layer-2 output
__device__ float g_res3[NN * 192];   // h2 @ resW3
__device__ float g_rst3[NN * 192];   // layer-3 output (pre-mean)
__device__ float g_el[NN * 6];
__device__ float g_er[NN * 6];
__device__ int   g_offs[NN + 1];
__device__ int   g_deg[NN];
__device__ int   g_cur[NN];
__device__ int   g_csrc[EE];         // src node per incoming edge, bucketed by dst

// ---------------- CSR build -------------------------------------------------
__global__ void k_zero(int n) {
    int i = blockIdx.x * blockDim.x + threadIdx.x;
    if (i < n) { g_deg[i] = 0; g_cur[i] = 0; }
}

__global__ void k_deg(const int* __restrict__ dst, int e) {
    int i = blockIdx.x * blockDim.x + threadIdx.x;
    if (i < e) atomicAdd(&g_deg[dst[i]], 1);
}

// single-block scan: serial-per-thread + warp-shuffle block scan (2 barriers)
__global__ void k_scan(int n) {
    __shared__ int ws[32];
    int t = threadIdx.x;
    int per = (n + 1023) / 1024;
    int start = t * per;
    int end = min(start + per, n);

    int sum = 0;
    for (int i = start; i < end; i++) sum += g_deg[i];

    int lane = t & 31, wid = t >> 5;
    int v = sum;
#pragma unroll
    for (int o = 1; o < 32; o <<= 1) {
        int u = __shfl_up_sync(0xffffffffu, v, o);
        if (lane >= o) v += u;
    }
    if (lane == 31) ws[wid] = v;
    __syncthreads();
    if (wid == 0) {
        int s = ws[lane];
#pragma unroll
        for (int o = 1; o < 32; o <<= 1) {
            int u = __shfl_up_sync(0xffffffffu, s, o);
            if (lane >= o) s += u;
        }
        ws[lane] = s;
    }
    __syncthreads();

    int warp_base = wid ? ws[wid - 1] : 0;
    int run = warp_base + v - sum;          // exclusive prefix for this thread
    for (int i = start; i < end; i++) {
        g_offs[i] = run;
        run += g_deg[i];
    }
    if (t == 0) g_offs[n] = ws[31];
}

__global__ void k_fill(const int* __restrict__ src, const int* __restrict__ dst, int e) {
    int i = blockIdx.x * blockDim.x + threadIdx.x;
    if (i < e) {
        int d = dst[i];
        int p = g_offs[d] + atomicAdd(&g_cur[d], 1);
        g_csrc[p] = src[i];
    }
}

// ---------------- tf32 helpers ----------------------------------------------
__device__ __forceinline__ float to_tf32(float x) {
    uint32_t u;
    asm("cvt.rna.tf32.f32 %0, %1;" : "=r"(u) : "f"(x));
    return __uint_as_float(u);
}

__device__ __forceinline__ void mma8(float* c, uint32_t a0, uint32_t a1,
                                     uint32_t a2, uint32_t a3,
                                     uint32_t b0, uint32_t b1) {
    asm volatile(
        "mma.sync.aligned.m16n8k8.row.col.f32.tf32.tf32.f32 "
        "{%0,%1,%2,%3}, {%4,%5,%6,%7}, {%8,%9}, {%0,%1,%2,%3};"
        : "+f"(c[0]), "+f"(c[1]), "+f"(c[2]), "+f"(c[3])
        : "r"(a0), "r"(a1), "r"(a2), "r"(a3), "r"(b0), "r"(b1));
}

// ---------------- tf32 tensor-core GEMM + fused epilogue --------------------
// C[n][M] = A[n][128] @ W[128][M]; block 64 rows x FULL width M (grid.y = 1,
// A staged exactly once per GEMM). 8 warps: 4 m-groups x 2 n-groups,
// warp tile 16 x M/2 (NT = M/16 n-tiles, HPW = M/64 heads per warp).
// W staged in 32-k chunks (R11's measured-best structure).
// Epilogue options: write_c (fp32 C for resW3), do_attn (half2 feat + el/er).
template<int M>
__global__ void k_gemm(const float* __restrict__ A, const float* __restrict__ W,
                       float* __restrict__ C, int n,
                       const float* __restrict__ al, const float* __restrict__ ar,
                       int write_c, int do_attn) {
    constexpr int TW = M / 2;      // warp n-width
    constexpr int NT = TW / 8;     // n-tiles per warp
    constexpr int HPW = TW / 32;   // heads per warp
    constexpr int H = M / 32;      // total heads
    constexpr int WROW = M + 8;    // Ws stride; (M+8)&31==8 -> bank 8tig+g, conflict-free

    __shared__ float As[64][132];  // fragment loads: bank = 4g+tig, conflict-free
    __shared__ float Ws[32][WROW];

    int row0 = blockIdx.x * 64;
    int t = threadIdx.x;
    int lane = t & 31, w = t >> 5;
    int wm = w & 3;                // 4 m-groups of 16 rows
    int wn = w >> 2;               // 2 n-groups of TW cols
    int g = lane >> 2, tig = lane & 3;

    // stage full A tile (64x128), converting to tf32
#pragma unroll
    for (int i = t; i < 64 * 32; i += 256) {
        int r = i >> 5, c4 = i & 31;
        int gr = row0 + r;
        float4 v = make_float4(0.f, 0.f, 0.f, 0.f);
        if (gr < n) v = *(const float4*)&A[(size_t)gr * 128 + c4 * 4];
        v.x = to_tf32(v.x); v.y = to_tf32(v.y);
        v.z = to_tf32(v.z); v.w = to_tf32(v.w);
        *(float4*)&As[r][c4 * 4] = v;
    }

    float acc[NT][4] = {};         // [n-tile][c-frag]

    for (int k0 = 0; k0 < 128; k0 += 32) {
        __syncthreads();
        // stage W chunk (32 k x M cols), converting to tf32
#pragma unroll
        for (int i = t; i < 32 * (M / 4); i += 256) {
            int kk = i / (M / 4), c4 = i % (M / 4);
            float4 v = *(const float4*)&W[(size_t)(k0 + kk) * M + c4 * 4];
            v.x = to_tf32(v.x); v.y = to_tf32(v.y);
            v.z = to_tf32(v.z); v.w = to_tf32(v.w);
            *(float4*)&Ws[kk][c4 * 4] = v;
        }
        __syncthreads();

#pragma unroll
        for (int ks = 0; ks < 4; ks++) {
            int kb = k0 + ks * 8;  // global k for As
            int kl = ks * 8;       // local k for Ws
            int ra = wm * 16 + g;
            uint32_t a0 = __float_as_uint(As[ra][kb + tig]);
            uint32_t a1 = __float_as_uint(As[ra + 8][kb + tig]);
            uint32_t a2 = __float_as_uint(As[ra][kb + tig + 4]);
            uint32_t a3 = __float_as_uint(As[ra + 8][kb + tig + 4]);
#pragma unroll
            for (int nt = 0; nt < NT; nt++) {
                int cb = wn * TW + nt * 8 + g;
                uint32_t b0 = __float_as_uint(Ws[kl + tig][cb]);
                uint32_t b1 = __float_as_uint(Ws[kl + tig + 4][cb]);
                mma8(acc[nt], a0, a1, a2, a3, b0, b1);
            }
        }
    }

    int r_lo = row0 + wm * 16 + g;
    int r_hi = r_lo + 8;

    if (write_c) {
#pragma unroll
        for (int nt = 0; nt < NT; nt++) {
            int c = wn * TW + nt * 8 + 2 * tig;
            if (r_lo < n)
                *(float2*)&C[(size_t)r_lo * M + c] = make_float2(acc[nt][0], acc[nt][1]);
            if (r_hi < n)
                *(float2*)&C[(size_t)r_hi * M + c] = make_float2(acc[nt][2], acc[nt][3]);
        }
    }

    if (do_attn) {
#pragma unroll
        for (int hg = 0; hg < HPW; hg++) {
            int h = wn * HPW + hg;         // global head index
            float pel_lo = 0.f, per_lo = 0.f, pel_hi = 0.f, per_hi = 0.f;
#pragma unroll
            for (int nt4 = 0; nt4 < 4; nt4++) {
                int nt = hg * 4 + nt4;
                int ci = nt4 * 8 + 2 * tig;    // col within head
                float2 alv = *(const float2*)&al[h * 32 + ci];
                float2 arv = *(const float2*)&ar[h * 32 + ci];
                pel_lo += acc[nt][0] * alv.x + acc[nt][1] * alv.y;
                per_lo += acc[nt][0] * arv.x + acc[nt][1] * arv.y;
                pel_hi += acc[nt][2] * alv.x + acc[nt][3] * alv.y;
                per_hi += acc[nt][2] * arv.x + acc[nt][3] * arv.y;

                __half2 plo = __floats2half2_rn(acc[nt][0], acc[nt][1]);
                __half2 phi = __floats2half2_rn(acc[nt][2], acc[nt][3]);
                int hw = nt4 * 4 + tig;        // half2 index within head
                if (r_lo < n) g_feat_h2[((size_t)r_lo * H + h) * 16 + hw] = plo;
                if (r_hi < n) g_feat_h2[((size_t)r_hi * H + h) * 16 + hw] = phi;
            }
#pragma unroll
            for (int o = 1; o < 4; o <<= 1) {
                pel_lo += __shfl_xor_sync(0xffffffffu, pel_lo, o);
                per_lo += __shfl_xor_sync(0xffffffffu, per_lo, o);
                pel_hi += __shfl_xor_sync(0xffffffffu, pel_hi, o);
                per_hi += __shfl_xor_sync(0xffffffffu, per_hi, o);
            }
            if (tig == 0) {
                if (r_lo < n) { g_el[r_lo * H + h] = pel_lo; g_er[r_lo * H + h] = per_lo; }
                if (r_hi < n) { g_el[r_hi * H + h] = pel_hi; g_er[r_hi * H + h] = per_hi; }
            }
        }
    }
}

// ---------------- fused aggregation: inline exp(leaky(el+er)) ---------------
// HG heads handled per task; LPT = 8*HG lanes per task.
//   H=4: HG=4 -> warp per node (csrc broadcast once per node).
//   H=6: HG=2 -> half-warp per (node, head-pair).
template<int H, int HG>
__global__ void k_aggf(const float* __restrict__ residual,  // [n][H*32] or null
                       const float* __restrict__ bias,      // [H*32]
                       float* __restrict__ out,             // [n][H*32]
                       int n, int do_relu) {
    constexpr int LPT = 8 * HG;       // lanes per task
    constexpr int TPW = 32 / LPT;     // tasks per warp
    constexpr int NB = H / HG;        // head-blocks per node

    int gwarp = (blockIdx.x * blockDim.x + threadIdx.x) >> 5;
    int lane = threadIdx.x & 31;
    int sub = lane / LPT;
    int sl = lane % LPT;
    int task = gwarp * TPW + sub;
    if (task >= n * NB) return;

    int v = task / NB;
    int hb = (task % NB) * HG;
    int h = hb + (sl >> 3);
    int fp = sl & 7;

    float er_d = g_er[v * H + h];
    int beg = g_offs[v], end = g_offs[v + 1];

    float a0 = 0.f, a1 = 0.f, a2 = 0.f, a3 = 0.f, den = 0.f;
#pragma unroll 4
    for (int i = beg; i < end; i++) {
        int s = g_csrc[i];
        float x = g_el[s * H + h] + er_d;
        x = (x > 0.f) ? x : 0.2f * x;
        float wgt = __expf(x);
        den += wgt;
        uint2 raw = *(const uint2*)&g_feat_h2[((size_t)s * H + h) * 16 + fp * 2];
        float2 f0 = __half22float2(*(const __half2*)&raw.x);
        float2 f1 = __half22float2(*(const __half2*)&raw.y);
        a0 = fmaf(wgt, f0.x, a0);
        a1 = fmaf(wgt, f0.y, a1);
        a2 = fmaf(wgt, f1.x, a2);
        a3 = fmaf(wgt, f1.y, a3);
    }
    float inv = 1.f / fmaxf(den, 1e-9f);
    a0 *= inv; a1 *= inv; a2 *= inv; a3 *= inv;

    size_t o = ((size_t)v * H + h) * 32 + fp * 4;
    if (residual) {
        float4 r4 = *(const float4*)&residual[o];
        a0 += r4.x; a1 += r4.y; a2 += r4.z; a3 += r4.w;
    }
    float4 b4 = *(const float4*)&bias[h * 32 + fp * 4];
    a0 += b4.x; a1 += b4.y; a2 += b4.z; a3 += b4.w;
    if (do_relu) {
        a0 = fmaxf(a0, 0.f); a1 = fmaxf(a1, 0.f);
        a2 = fmaxf(a2, 0.f); a3 = fmaxf(a3, 0.f);
    }
    *(float4*)&out[o] = make_float4(a0, a1, a2, a3);
}

// ---------------- mean over 6 heads -----------------------------------------
__global__ void k_mean(float* __restrict__ out, int n) {
    int i = blockIdx.x * blockDim.x + threadIdx.x;
    if (i < n * 32) {
        int v = i >> 5, k = i & 31;
        float s = 0.f;
#pragma unroll
        for (int h = 0; h < 6; h++) s += g_rst3[(size_t)v * 192 + h * 32 + k];
        out[i] = s * (1.f / 6.f);
    }
}

// ---------------- launch ----------------------------------------------------
extern "C" void kernel_launch(void* const* d_in, const int* in_sizes, int n_in,
                              void* d_out, int out_size) {
    const float* x     = (const float*)d_in[0];
    const int*   src   = (const int*)d_in[1];
    const int*   dst   = (const int*)d_in[2];
    const float* W1    = (const float*)d_in[3];
    const float* al1   = (const float*)d_in[4];
    const float* ar1   = (const float*)d_in[5];
    const float* b1    = (const float*)d_in[6];
    const float* W2    = (const float*)d_in[7];
    const float* al2   = (const float*)d_in[8];
    const float* ar2   = (const float*)d_in[9];
    const float* b2    = (const float*)d_in[10];
    const float* W3    = (const float*)d_in[11];
    const float* al3   = (const float*)d_in[12];
    const float* ar3   = (const float*)d_in[13];
    const float* b3    = (const float*)d_in[14];
    const float* resW3 = (const float*)d_in[15];

    int n = in_sizes[0] / 128;   // 50000
    int e = in_sizes[1];         // 850000

    float *p_h1, *p_h2, *p_res3, *p_rst3;
    cudaGetSymbolAddress((void**)&p_h1,   g_h1);
    cudaGetSymbolAddress((void**)&p_h2,   g_h2);
    cudaGetSymbolAddress((void**)&p_res3, g_res3);
    cudaGetSymbolAddress((void**)&p_rst3, g_rst3);

    // CSR build (graph fixed, but rebuilt deterministically each replay)
    k_zero<<<(n + 255) / 256, 256>>>(n);
    k_deg<<<(e + 255) / 256, 256>>>(dst, e);
    k_scan<<<1, 1024>>>(n);
    k_fill<<<(e + 255) / 256, 256>>>(src, dst, e);

    int gemm_blocks = (n + 63) / 64;

    // agg grids: H=4 -> n warps; H=6 -> 3n half-warps
    int agg4_blocks = (n * 32 + 255) / 256;
    int agg6_blocks = (((n * 3 + 1) / 2) * 32 + 255) / 256;

    // ---- layer 1: H=4 ----
    k_gemm<128><<<gemm_blocks, 256>>>(x, W1, nullptr, n, al1, ar1, 0, 1);
    k_aggf<4, 4><<<agg4_blocks, 256>>>(nullptr, b1, p_h1, n, 1);

    // ---- layer 2: H=4, identity residual ----
    k_gemm<128><<<gemm_blocks, 256>>>(p_h1, W2, nullptr, n, al2, ar2, 0, 1);
    k_aggf<4, 4><<<agg4_blocks, 256>>>(p_h1, b2, p_h2, n, 1);

    // ---- layer 3: H=6, projected residual, no relu ----
    k_gemm<192><<<gemm_blocks, 256>>>(p_h2, resW3, p_res3, n, nullptr, nullptr, 1, 0);
    k_gemm<192><<<gemm_blocks, 256>>>(p_h2, W3, nullptr, n, al3, ar3, 0, 1);
    k_aggf<6, 2><<<agg6_blocks, 256>>>(p_res3, b3, p_rst3, n, 0);

    // ---- mean over heads ----
    k_mean<<<(n * 32 + 255) / 256, 256>>>((float*)d_out, n);
}